// round 16
// baseline (speedup 1.0000x reference)
#include <cuda_runtime.h>

// Problem constants
#define Bq    256
#define Tq    512
#define INq   4
#define PAIRS 768      // M*D
#define NSq   64
#define Hq    128
#define G3q   384      // 3*H
#define NTHR  384
#define NCTA  128      // 2 batches per CTA
#define BT_TOT (Bq*Tq)
#define WREG  96       // W_hh rows cached in registers

// Packed f32x2 helpers (Blackwell)
#define FMA2(d,a,b)  asm("fma.rn.f32x2 %0, %1, %2, %0;" : "+l"(d) : "l"(a), "l"(b))
#define ADD2(d,a,b)  asm("add.rn.f32x2 %0, %1, %2;" : "=l"(d) : "l"(a), "l"(b))
#define PACK2(d,x,y) asm("mov.b64 %0, {%1, %2};" : "=l"(d) : "f"(x), "f"(y))
#define UNPK2(x,y,d) asm("mov.b64 {%0, %1}, %2;" : "=f"(x), "=f"(y) : "l"(d))

struct __align__(16) Smem {
    float  sST2[NSq * PAIRS];  // blocked: [nb][j][4] = (w[n0][p0], w[n0][p1], w[n1][p0], w[n1][p1])
    float2 sKi[PAIRS];         // K interleaved: (k_b0, k_b1) per pair
    float2 sSdup[2 * NSq];     // s duplicated: [b*64+n] = (s, s)
    float  sGh[2 * G3q];       // gh: [b][col]  (gh for step t, computed at E(t-1))
    float  sH[2 * Hq];         // hidden state
    float  sWih[4 * G3q];      // W_ih row-major
    float  sBih[G3q];
    float  sBhh[G3q];
    float  sWdT[3 * Hq];       // Wd transposed, padded (col 127 = 0)
    float  sRed[12 * 128];     // K.A partials (unscaled): [warp][b*64+n]
    float  sEncW[32];          // per-warp K max: [w*2+b] (w<12)
    float  sLogW[32];          // logit partials: [w*4+m] (w<8)
    float  sQpart[4];          // warp partials of |s|^2
    float  sBd[4];
    float  sX[8];              // x_t both batches
    float  sY[4];              // y, parity double-buffered: [par*2+b]
    float  sErr[4];
    float  sGate[16];          // gate, parity double-buffered: [par][b*4+m]
};

// Precomputed weight transforms
__device__ __align__(16) float g_ST2[NSq * PAIRS];  // blocked layout (see Smem::sST2)
__device__ __align__(16) float g_C[PAIRS];          // -0.5*(|U_p|^2+|S_p|^2)

__global__ void prep_kernel(const float* __restrict__ U,
                            const float* __restrict__ S) {
    int p = blockIdx.x * blockDim.x + threadIdx.x;
    if (p >= PAIRS) return;
    int j = p >> 1, e = p & 1;
    float cs = 0.f;
    for (int n = 0; n < NSq; n++) {
        float v = S[p * NSq + n];
        cs += v * v;
        int nb = n >> 1, o = n & 1;
        g_ST2[(nb * 384 + j) * 4 + o * 2 + e] = v;
    }
    float cu = 0.f;
    for (int i = 0; i < INq; i++) { float u = U[p * INq + i]; cu += u * u; }
    g_C[p] = -0.5f * (cu + cs);
}

__device__ __forceinline__ float sigmoid_fast(float v) {
    return 1.f / (1.f + __expf(-v));     // saturates safely at both ends
}
__device__ __forceinline__ float tanh_fast(float v) {
    float t = __expf(-2.f * fabsf(v));   // t in (0,1], no overflow
    float r = __fdividef(1.f - t, 1.f + t);
    return v < 0.f ? -r : r;
}

__global__ void __launch_bounds__(NTHR, 1)
scan_kernel(const float* __restrict__ x, const float* __restrict__ y,
            const float* __restrict__ U, const float* __restrict__ A,
            const float* __restrict__ Whh,
            const float* __restrict__ Wd, const float* __restrict__ bd,
            const float* __restrict__ Wih,
            const float* __restrict__ bih, const float* __restrict__ bhh,
            float* __restrict__ out) {
    extern __shared__ float smraw[];
    Smem* sm = reinterpret_cast<Smem*>(smraw);
    const int tid  = threadIdx.x;
    const int wid  = tid >> 5;
    const int lane = tid & 31;
    const int b0   = blockIdx.x * 2;

    // ---- persistent registers: W_hh column (rows 0..WREG-1) for col = tid
    float whh[WREG];
#pragma unroll
    for (int k = 0; k < WREG; k++) whh[k] = Whh[k * G3q + tid];

    // U rows + C for this thread's two adjacent pairs p0=2t, p1=2t+1
    const int p0 = 2 * tid, p1 = 2 * tid + 1;
    float Ua[4], Ub[4];
#pragma unroll
    for (int i = 0; i < 4; i++) { Ua[i] = U[p0 * 4 + i]; Ub[i] = U[p1 * 4 + i]; }
    const float C0 = g_C[p0], C1 = g_C[p1];

    // ---- one-time smem init ----
    {
        const float4* src = reinterpret_cast<const float4*>(g_ST2);
        float4* dst = reinterpret_cast<float4*>(sm->sST2);
        for (int i = tid; i < (NSq * PAIRS) / 4; i += NTHR) dst[i] = src[i];
    }
    for (int i = tid; i < 4 * G3q; i += NTHR) sm->sWih[i] = Wih[i];
    for (int i = tid; i < G3q; i += NTHR) {
        float v = bhh[i];
        sm->sBih[i] = bih[i];
        sm->sBhh[i] = v;
        sm->sGh[i] = v;           // gh(0): h=0 -> gh = bhh
        sm->sGh[G3q + i] = v;
    }
    for (int i = tid; i < 3 * Hq; i += NTHR) {
        int m = i >> 7, j = i & 127;
        sm->sWdT[m * 128 + j] = (j < 127) ? Wd[j * 3 + m] : 0.f;
    }
    if (tid < 4) sm->sBd[tid] = (tid < 3) ? bd[tid] : 0.f;
    for (int i = tid; i < 2 * NSq; i += NTHR) sm->sSdup[i] = make_float2(0.f, 0.f);
    for (int i = tid; i < 2 * Hq; i += NTHR) sm->sH[i] = 0.f;
    if (tid < 16) {
        int mm = tid & 3;
        sm->sGate[tid] = (mm == 0) ? 0.3333f : (mm == 1) ? 0.3333f : (mm == 2) ? 0.3334f : 0.f;
    }
    if (tid < 2) sm->sErr[tid] = 1.f;
    if (tid < 4) sm->sQpart[tid] = 0.f;
    if (tid < 8) {
        int b = tid >> 2, i = tid & 3;
        sm->sX[b * 4 + i] = x[(size_t)(b0 + b) * Tq * INq + i];
    }
    if (tid >= 8 && tid < 10) {
        int b = tid - 8;
        sm->sY[0 * 2 + b] = y[(size_t)(b0 + b) * Tq];   // parity 0 slot for t=0
    }
    __syncthreads();

    for (int t = 0; t < Tq; t++) {
        // ===== Region A: K = exp(C + base + x.U + s.S), per-warp enc max =====
        {
            float q0 = sm->sQpart[0] + sm->sQpart[1];
            float q1 = sm->sQpart[2] + sm->sQpart[3];
            float xa0 = sm->sX[0], xa1 = sm->sX[1], xa2 = sm->sX[2], xa3 = sm->sX[3];
            float xb0 = sm->sX[4], xb1 = sm->sX[5], xb2 = sm->sX[6], xb3 = sm->sX[7];
            float base0 = -0.5f * (xa0*xa0 + xa1*xa1 + xa2*xa2 + xa3*xa3 + q0);
            float base1 = -0.5f * (xb0*xb0 + xb1*xb1 + xb2*xb2 + xb3*xb3 + q1);

            // packed accumulators: lanes = (pair p0, pair p1)
            unsigned long long acc0a = 0ull, acc0b = 0ull, acc1a = 0ull, acc1b = 0ull;
#pragma unroll
            for (int nb = 0; nb < 32; nb += 2) {
                ulonglong2 w0 = *reinterpret_cast<const ulonglong2*>(&sm->sST2[(nb * 384 + tid) * 4]);
                ulonglong2 s0 = *reinterpret_cast<const ulonglong2*>(&sm->sSdup[2 * nb]);
                ulonglong2 s1 = *reinterpret_cast<const ulonglong2*>(&sm->sSdup[64 + 2 * nb]);
                FMA2(acc0a, w0.x, s0.x); FMA2(acc0a, w0.y, s0.y);
                FMA2(acc1a, w0.x, s1.x); FMA2(acc1a, w0.y, s1.y);
                ulonglong2 w1 = *reinterpret_cast<const ulonglong2*>(&sm->sST2[((nb + 1) * 384 + tid) * 4]);
                ulonglong2 t0 = *reinterpret_cast<const ulonglong2*>(&sm->sSdup[2 * nb + 2]);
                ulonglong2 t1 = *reinterpret_cast<const ulonglong2*>(&sm->sSdup[64 + 2 * nb + 2]);
                FMA2(acc0b, w1.x, t0.x); FMA2(acc0b, w1.y, t0.y);
                FMA2(acc1b, w1.x, t1.x); FMA2(acc1b, w1.y, t1.y);
            }
            ADD2(acc0a, acc0a, acc0b);
            ADD2(acc1a, acc1a, acc1b);
            float a00, a10, a01, a11;
            UNPK2(a00, a10, acc0a);   // batch0: (p0, p1)
            UNPK2(a01, a11, acc1a);   // batch1: (p0, p1)

            float xu00 = xa0*Ua[0] + xa1*Ua[1] + xa2*Ua[2] + xa3*Ua[3];
            float xu01 = xb0*Ua[0] + xb1*Ua[1] + xb2*Ua[2] + xb3*Ua[3];
            float xu10 = xa0*Ub[0] + xa1*Ub[1] + xa2*Ub[2] + xa3*Ub[3];
            float xu11 = xb0*Ub[0] + xb1*Ub[1] + xb2*Ub[2] + xb3*Ub[3];
            float k00 = __expf(C0 + base0 + xu00 + a00);
            float k01 = __expf(C0 + base1 + xu01 + a01);
            float k10 = __expf(C1 + base0 + xu10 + a10);
            float k11 = __expf(C1 + base1 + xu11 + a11);
            *reinterpret_cast<float4*>(&sm->sKi[p0]) = make_float4(k00, k01, k10, k11);
            float v0 = fmaxf(k00, k10), v1 = fmaxf(k01, k11);
#pragma unroll
            for (int off = 16; off; off >>= 1) {
                v0 = fmaxf(v0, __shfl_xor_sync(0xffffffffu, v0, off));
                v1 = fmaxf(v1, __shfl_xor_sync(0xffffffffu, v1, off));
            }
            if (lane == 0) { sm->sEncW[wid * 2] = v0; sm->sEncW[wid * 2 + 1] = v1; }
        }
        __syncthreads();

        // ===== Region BD: K.A partials (packed f32x2) + GRU + logit partials =====
        {
            const int half = lane >> 4, li = lane & 15;
            const int pbase = wid * 64;
            // packed accumulators: (n=4li..4li+1) and (4li+2..4li+3) per batch
            unsigned long long b0n01 = 0ull, b0n23 = 0ull, b1n01 = 0ull, b1n23 = 0ull;
            const ulonglong2* A2 = reinterpret_cast<const ulonglong2*>(A);
#pragma unroll 8
            for (int i = 0; i < 32; i++) {
                int p = pbase + 2 * i + half;
                ulonglong2 av = __ldg(&A2[p * 16 + li]);
                float2 kk = sm->sKi[p];
                unsigned long long k0d, k1d;
                PACK2(k0d, kk.x, kk.x);
                PACK2(k1d, kk.y, kk.y);
                FMA2(b0n01, k0d, av.x); FMA2(b0n23, k0d, av.y);
                FMA2(b1n01, k1d, av.x); FMA2(b1n23, k1d, av.y);
            }
            // combine even/odd-p halves (packed shuffles + packed adds)
            unsigned long long tmp;
            tmp = __shfl_xor_sync(0xffffffffu, b0n01, 16); ADD2(b0n01, b0n01, tmp);
            tmp = __shfl_xor_sync(0xffffffffu, b0n23, 16); ADD2(b0n23, b0n23, tmp);
            tmp = __shfl_xor_sync(0xffffffffu, b1n01, 16); ADD2(b1n01, b1n01, tmp);
            tmp = __shfl_xor_sync(0xffffffffu, b1n23, 16); ADD2(b1n23, b1n23, tmp);
            if (lane < 16) {
                *reinterpret_cast<ulonglong2*>(&sm->sRed[wid * 128 +      4 * li]) = make_ulonglong2(b0n01, b0n23);
                *reinterpret_cast<ulonglong2*>(&sm->sRed[wid * 128 + 64 + 4 * li]) = make_ulonglong2(b1n01, b1n23);
            }

            // GRU elementwise + logit partials (threads 0..255; warp covers 32 j's of one b)
            if (tid < 256) {
                int b = tid >> 7, j = tid & 127;
                float e0 = fmaxf(fmaxf(sm->sEncW[0*2+b], sm->sEncW[1*2+b]),
                                 fmaxf(sm->sEncW[2*2+b], sm->sEncW[3*2+b]));
                float e1 = fmaxf(fmaxf(sm->sEncW[4*2+b], sm->sEncW[5*2+b]),
                                 fmaxf(sm->sEncW[6*2+b], sm->sEncW[7*2+b]));
                float e2 = fmaxf(fmaxf(sm->sEncW[8*2+b], sm->sEncW[9*2+b]),
                                 fmaxf(sm->sEncW[10*2+b], sm->sEncW[11*2+b]));
                float er = sm->sErr[b];
                float gir = sm->sBih[j]
                          + e0 * sm->sWih[j]             + e1 * sm->sWih[G3q + j]
                          + e2 * sm->sWih[2*G3q + j]     + er * sm->sWih[3*G3q + j];
                float giz = sm->sBih[128 + j]
                          + e0 * sm->sWih[128 + j]           + e1 * sm->sWih[G3q + 128 + j]
                          + e2 * sm->sWih[2*G3q + 128 + j]   + er * sm->sWih[3*G3q + 128 + j];
                float gin = sm->sBih[256 + j]
                          + e0 * sm->sWih[256 + j]           + e1 * sm->sWih[G3q + 256 + j]
                          + e2 * sm->sWih[2*G3q + 256 + j]   + er * sm->sWih[3*G3q + 256 + j];
                float ghr = sm->sGh[b * G3q + j];
                float ghz = sm->sGh[b * G3q + 128 + j];
                float ghn = sm->sGh[b * G3q + 256 + j];
                float rr = sigmoid_fast(gir + ghr);
                float zz = sigmoid_fast(giz + ghz);
                float nn = tanh_fast(gin + rr * ghn);
                float hv = (1.f - zz) * nn + zz * sm->sH[b * 128 + j];
                sm->sH[b * 128 + j] = hv;
                // logit partials from the register-resident h
                float lm0 = hv * sm->sWdT[j];          // col 127 weight is 0
                float lm1 = hv * sm->sWdT[128 + j];
                float lm2 = hv * sm->sWdT[256 + j];
#pragma unroll
                for (int off = 16; off; off >>= 1) {
                    lm0 += __shfl_xor_sync(0xffffffffu, lm0, off);
                    lm1 += __shfl_xor_sync(0xffffffffu, lm1, off);
                    lm2 += __shfl_xor_sync(0xffffffffu, lm2, off);
                }
                if (lane == 0) {
                    sm->sLogW[wid * 4 + 0] = lm0;
                    sm->sLogW[wid * 4 + 1] = lm1;
                    sm->sLogW[wid * 4 + 2] = lm2;
                }
            }
        }
        __syncthreads();

        // ===== Region E: softmax(redundant) + s_new reduce + gh(t+1) GEMV =====
        {
            // gh(t+1) = h(t) @ W_hh + b_hh : all 384 threads, col = tid
            float acc0 = sm->sBhh[tid];
            float acc1 = acc0;
#pragma unroll
            for (int k = 0; k < WREG; k += 4) {
                float4 h0 = *reinterpret_cast<const float4*>(&sm->sH[k]);
                float4 h1 = *reinterpret_cast<const float4*>(&sm->sH[128 + k]);
                acc0 += h0.x*whh[k] + h0.y*whh[k+1] + h0.z*whh[k+2] + h0.w*whh[k+3];
                acc1 += h1.x*whh[k] + h1.y*whh[k+1] + h1.z*whh[k+2] + h1.w*whh[k+3];
            }
#pragma unroll
            for (int k = WREG; k < Hq; k += 4) {
                float4 h0 = *reinterpret_cast<const float4*>(&sm->sH[k]);
                float4 h1 = *reinterpret_cast<const float4*>(&sm->sH[128 + k]);
                float w0 = __ldg(&Whh[(k + 0) * G3q + tid]);
                float w1 = __ldg(&Whh[(k + 1) * G3q + tid]);
                float w2 = __ldg(&Whh[(k + 2) * G3q + tid]);
                float w3 = __ldg(&Whh[(k + 3) * G3q + tid]);
                acc0 += h0.x*w0 + h0.y*w1 + h0.z*w2 + h0.w*w3;
                acc1 += h1.x*w0 + h1.y*w1 + h1.z*w2 + h1.w*w3;
            }
            sm->sGh[tid]       = acc0;
            sm->sGh[G3q + tid] = acc1;

            if (tid < 128) {
                int b = tid >> 6, n = tid & 63;
                // per-m sums over the 4 warps of each m
                float ns0 = sm->sRed[0*128 + tid] + sm->sRed[1*128 + tid]
                          + sm->sRed[2*128 + tid] + sm->sRed[3*128 + tid];
                float ns1 = sm->sRed[4*128 + tid] + sm->sRed[5*128 + tid]
                          + sm->sRed[6*128 + tid] + sm->sRed[7*128 + tid];
                float ns2 = sm->sRed[8*128 + tid] + sm->sRed[9*128 + tid]
                          + sm->sRed[10*128 + tid] + sm->sRed[11*128 + tid];
                // redundant gate computation (broadcast reads, fully parallel)
                float l0 = sm->sBd[0] + sm->sLogW[(b*4+0)*4+0] + sm->sLogW[(b*4+1)*4+0]
                                      + sm->sLogW[(b*4+2)*4+0] + sm->sLogW[(b*4+3)*4+0];
                float l1 = sm->sBd[1] + sm->sLogW[(b*4+0)*4+1] + sm->sLogW[(b*4+1)*4+1]
                                      + sm->sLogW[(b*4+2)*4+1] + sm->sLogW[(b*4+3)*4+1];
                float l2 = sm->sBd[2] + sm->sLogW[(b*4+0)*4+2] + sm->sLogW[(b*4+1)*4+2]
                                      + sm->sLogW[(b*4+2)*4+2] + sm->sLogW[(b*4+3)*4+2];
                float mx = fmaxf(l0, fmaxf(l1, l2));
                float e0 = __expf(l0 - mx), e1 = __expf(l1 - mx), e2 = __expf(l2 - mx);
                float inv = 1.f / (e0 + e1 + e2);
                float theta = sigmoid_fast(sm->sH[b * 128 + 127]);
                float omt = 1.f - theta;
                int par = t & 1;
                float g0 = e0 * inv * theta + sm->sGate[par * 8 + b * 4 + 0] * omt;
                float g1 = e1 * inv * theta + sm->sGate[par * 8 + b * 4 + 1] * omt;
                float g2 = e2 * inv * theta + sm->sGate[par * 8 + b * 4 + 2] * omt;
                float s = g0 * ns0 + g1 * ns1 + g2 * ns2;
                sm->sSdup[tid] = make_float2(s, s);    // duplicated for packed region A
                float sq = s * s;
#pragma unroll
                for (int off = 16; off; off >>= 1)
                    sq += __shfl_xor_sync(0xffffffffu, sq, off);
                if (lane == 0) sm->sQpart[wid] = sq;
                if (n == 0) {
                    int np = par ^ 1;
                    sm->sGate[np * 8 + b * 4 + 0] = g0;
                    sm->sGate[np * 8 + b * 4 + 1] = g1;
                    sm->sGate[np * 8 + b * 4 + 2] = g2;
                    float pen = g0 * (1.f - g0) + g1 * (1.f - g1) + g2 * (1.f - g2);
                    out[BT_TOT + (size_t)(b0 + b) * Tq + t] = pen;
                }
                if (n == 63) {
                    out[(size_t)(b0 + b) * Tq + t] = s;   // pred
                    sm->sErr[b] = s - sm->sY[(t & 1) * 2 + b];
                }
            } else if (t + 1 < Tq) {
                int q2 = tid - 128;
                if (q2 < 8) {
                    int b = q2 >> 2, i = q2 & 3;
                    sm->sX[b * 4 + i] = x[(size_t)(b0 + b) * Tq * INq + (size_t)(t + 1) * INq + i];
                } else if (q2 < 10) {
                    int b = q2 - 8;
                    sm->sY[((t + 1) & 1) * 2 + b] = y[(size_t)(b0 + b) * Tq + (t + 1)];
                }
            }
        }
        __syncthreads();
    }
}

extern "C" void kernel_launch(void* const* d_in, const int* in_sizes, int n_in,
                              void* d_out, int out_size) {
    const float* x   = (const float*)d_in[0];
    const float* y   = (const float*)d_in[1];
    const float* U   = (const float*)d_in[2];
    const float* S   = (const float*)d_in[3];
    const float* A   = (const float*)d_in[4];
    const float* Wih = (const float*)d_in[5];
    const float* Whh = (const float*)d_in[6];
    const float* bih = (const float*)d_in[7];
    const float* bhh = (const float*)d_in[8];
    const float* Wd  = (const float*)d_in[9];
    const float* bd  = (const float*)d_in[10];
    float* out = (float*)d_out;

    cudaFuncSetAttribute(scan_kernel, cudaFuncAttributeMaxDynamicSharedMemorySize,
                         (int)sizeof(Smem));

    prep_kernel<<<3, 256>>>(U, S);
    scan_kernel<<<NCTA, NTHR, sizeof(Smem)>>>(x, y, U, A, Whh, Wd, bd, Wih, bih, bhh, out);
}